// round 15
// baseline (speedup 1.0000x reference)
#include <cuda_runtime.h>
#include <math.h>

#define BB   512
#define PP   256
#define MAXW 0.1f
#define EPSI 1e-8f
#define NPGD 250
#define NPOW 20

#define RP        260                 // padded row length in floats (260 ≡ 4 mod 32 → conflict-free)
#define SROWS     128                 // rows of sigma kept in SMEM (rows 0..127)
#define SIG_WORDS (SROWS * RP)        // 33280
#define XS_OFF    SIG_WORDS           // current vector (w or power-iter v), 256 floats
#define VS_OFF    (SIG_WORDS + 256)   // staging vector, 256 floats
#define FL_OFF    (SIG_WORDS + 512)   // 2 ints: convergence flags (double-buffered)
#define SMEM_WORDS (SIG_WORDS + 544)
#define SMEM_BYTES (SMEM_WORDS * 4)   // 135296 B

#define FPSCALE 33554432.0f           // 2^25 fixed point for clamped sums (max 25.6 -> fits s32)
#define FPONE   33554432

// 32-lane butterfly sum (cold paths only: power iteration + epilogue)
__device__ __forceinline__ float bfly_add(float v) {
#pragma unroll
    for (int o = 16; o >= 1; o >>= 1) v += __shfl_xor_sync(0xffffffffu, v, o);
    return v;
}

// monotone float <-> u32 key (order-preserving), for REDUX-based min/max
__device__ __forceinline__ unsigned fkey(float f) {
    int i = __float_as_int(f);
    unsigned u = (unsigned)i;
    return (i >= 0) ? (u | 0x80000000u) : ~u;
}
__device__ __forceinline__ float funkey(unsigned u) {
    return __int_as_float((u & 0x80000000u) ? (int)(u ^ 0x80000000u) : (int)(~u));
}

// packed f32x2 FMA: acc.lo += a.lo*b.lo, acc.hi += a.hi*b.hi  (FFMA2, PTX-only)
__device__ __forceinline__ void fma2(unsigned long long& acc,
                                     unsigned long long a, unsigned long long b) {
    asm("fma.rn.f32x2 %0, %1, %2, %0;" : "+l"(acc) : "l"(a), "l"(b));
}
__device__ __forceinline__ float pairsum(unsigned long long p) {
    float lo, hi;
    asm("mov.b64 {%0, %1}, %2;" : "=f"(lo), "=f"(hi) : "l"(p));
    return lo + hi;
}

// Bracket-safeguarded Newton for sum(clip(vr - tau, 0, MAXW)) == 1.
// EXACTLY the solver from the validated 1507us PASS (R8 kernel) — bracket computed
// every call, warm start clamped into the bracket, 14-iter bisection-safeguarded.
__device__ __forceinline__ float solve_tau(const float (&vr)[8], float tau0, int warm) {
    float mn = fminf(fminf(fminf(vr[0], vr[1]), fminf(vr[2], vr[3])),
                     fminf(fminf(vr[4], vr[5]), fminf(vr[6], vr[7])));
    float mx = fmaxf(fmaxf(fmaxf(vr[0], vr[1]), fmaxf(vr[2], vr[3])),
                     fmaxf(fmaxf(vr[4], vr[5]), fmaxf(vr[6], vr[7])));
    mn = funkey(__reduce_min_sync(0xffffffffu, fkey(mn)));
    mx = funkey(__reduce_max_sync(0xffffffffu, fkey(mx)));
    float lo = mn - MAXW, hi = mx;           // s(lo)=25.6>=1, s(hi)=0<=1: valid bracket
    float tau = warm ? fminf(fmaxf(tau0, lo), hi) : 0.5f * (lo + hi);

    for (int i = 0; i < 14; i++) {
        float s = 0.f; int m = 0;
#pragma unroll
        for (int k = 0; k < 8; k++) {
            const float d = vr[k] - tau;
            s += fminf(fmaxf(d, 0.f), MAXW);
            m += (d > 0.f) && (d < MAXW);
        }
        int si = __float2int_rn(s * FPSCALE);
        si = __reduce_add_sync(0xffffffffu, si);
        m  = __reduce_add_sync(0xffffffffu, m);
        const int err = si - FPONE;
        if (err >= -1 && err <= 1) return tau;            // |s-1| small: done
        if (err > 0) lo = tau; else hi = tau;
        if (hi - lo < 1e-9f) break;
        float t = (m > 0) ? fmaf((float)err, (1.0f / FPSCALE) / (float)m, tau)
                          : 0.5f * (lo + hi);
        tau = (t > lo && t < hi) ? t : 0.5f * (lo + hi);  // safeguard
    }
    return 0.5f * (lo + hi);
}

// Mat-vec: y = sigma * x. Rows 0..127 from SMEM, rows 128..255 from register file
// rf2[32] (f32x2-packed). Thread t: row_lo=t>>2, row_hi=128+(t>>2), chunk=t&3,
// cols staggered per chunk so the 4 chunks of a row-group hit distinct bank groups.
__device__ __forceinline__ void matvec256(const float* __restrict__ sm,
                                          const unsigned long long (&rf2)[32],
                                          int sbase, int xbase, int chunk,
                                          float& Y0, float& Y1) {
    unsigned long long A0 = 0ull, B0 = 0ull, A1 = 0ull, B1 = 0ull;
#pragma unroll
    for (int i = 0; i < 16; i++) {
        const int cm = 4 * ((i + 2 * chunk) & 15);
        const ulonglong2 xv = *reinterpret_cast<const ulonglong2*>(&sm[xbase + cm]);
        const ulonglong2 sv = *reinterpret_cast<const ulonglong2*>(&sm[sbase + cm]);
        fma2(A0, sv.x, xv.x);
        fma2(B0, sv.y, xv.y);
        fma2(A1, rf2[2 * i + 0], xv.x);
        fma2(B1, rf2[2 * i + 1], xv.y);
    }
    float r0 = pairsum(A0) + pairsum(B0);
    float r1 = pairsum(A1) + pairsum(B1);
    r0 += __shfl_xor_sync(0xffffffffu, r0, 1);
    r1 += __shfl_xor_sync(0xffffffffu, r1, 1);
    r0 += __shfl_xor_sync(0xffffffffu, r0, 2);
    r1 += __shfl_xor_sync(0xffffffffu, r1, 2);
    Y0 = r0; Y1 = r1;
}

__global__ __launch_bounds__(512, 1)
void drb_kernel(const float* __restrict__ sigma,
                const float* __restrict__ beta,
                const float* __restrict__ wprev,
                const float* __restrict__ ll1,
                const float* __restrict__ ll2,
                float* __restrict__ out) {
    extern __shared__ float sm[];
    int* const smi = reinterpret_cast<int*>(sm);
    const int tid    = threadIdx.x;
    const int b      = blockIdx.x;
    const int chunk  = tid & 3;
    const int col0   = chunk * 64;
    const int row_lo = tid >> 2;          // 0..127
    const int row_hi = 128 + row_lo;      // 128..255
    const int lane   = tid & 31;
    const int wid    = tid >> 5;          // 0..15
    const int sbase  = row_lo * RP + col0;
    const int xbase  = XS_OFF + col0;

    const float lam1 = expf(ll1[0]);
    const float lam2 = expf(ll2[0]);

    const size_t gb = (size_t)b * PP * PP;

    // ---- register-resident half of sigma (rows 128..255), f32x2-packed, staggered ----
    unsigned long long rf2[32];
    {
        const float* grow = sigma + gb + (size_t)row_hi * PP + col0;
#pragma unroll
        for (int i = 0; i < 16; i++) {
            const int cm = 4 * ((i + 2 * chunk) & 15);
            const ulonglong2 v = *reinterpret_cast<const ulonglong2*>(&grow[cm]);
            rf2[2 * i + 0] = v.x;
            rf2[2 * i + 1] = v.y;
        }
    }

    // ---- SMEM-resident half of sigma (rows 0..127), padded rows ----
    for (int idx = tid; idx < SROWS * 64; idx += 512) {
        const int r = idx >> 6, c4 = idx & 63;
        const float4 v = *reinterpret_cast<const float4*>(&sigma[gb + (size_t)r * PP + c4 * 4]);
        *reinterpret_cast<float4*>(&sm[r * RP + c4 * 4]) = v;
    }

    const float beta0 = beta[b * PP + row_lo];
    const float beta1 = beta[b * PP + row_hi];
    const float wp0   = wprev[b * PP + row_lo];
    const float wp1   = wprev[b * PP + row_hi];

    // ---- power iteration: v0 = 1/sqrt(P) ----
    if (tid < 256) sm[XS_OFF + tid] = 0.0625f;
    __syncthreads();

    for (int it = 0; it < NPOW; it++) {
        float u0, u1;
        matvec256(sm, rf2, sbase, xbase, chunk, u0, u1);
        if (chunk == 0) { sm[VS_OFF + row_lo] = u0; sm[VS_OFF + row_hi] = u1; }
        __syncthreads();
        float ns = 0.f;
#pragma unroll
        for (int k = 0; k < 8; k++) {
            const float t = sm[VS_OFF + lane + 32 * k];
            ns = fmaf(t, t, ns);
        }
        ns = bfly_add(ns);
        const float inv = 1.0f / (sqrtf(ns) + EPSI);
        if (tid < 256) sm[XS_OFF + tid] = sm[VS_OFF + tid] * inv;
        __syncthreads();
    }

    // ---- lmax = v' S v, step = 1/(2 lmax + 2 lam2 + 1e-6) ----
    float step;
    {
        float u0, u1;
        matvec256(sm, rf2, sbase, xbase, chunk, u0, u1);
        if (chunk == 0) {
            sm[VS_OFF + row_lo] = u0 * sm[XS_OFF + row_lo];
            sm[VS_OFF + row_hi] = u1 * sm[XS_OFF + row_hi];
        }
        __syncthreads();
        float lm = 0.f;
#pragma unroll
        for (int k = 0; k < 8; k++) lm += sm[VS_OFF + lane + 32 * k];
        lm = bfly_add(lm);
        step = 1.0f / (2.0f * lm + 2.0f * lam2 + 1e-6f);
        if (tid < 256) sm[XS_OFF + tid] = 1.0f / 256.0f;   // w0 = 1/P
        if (tid < 2)   smi[FL_OFF + tid] = 0;              // convergence flags
        __syncthreads();
    }

    float tau_p = 0.f;
    int   have_warm = 0;
    float pw0 = 1.0f / 256.0f, pw1 = 1.0f / 256.0f;        // prev w for early-exit check
    const int kk   = wid >> 1;                              // vr reg this warp writes back
    const int wsel = ((lane >> 4) == (wid & 1));

    // ---- projected gradient descent ----
    for (int it = 0; it < NPGD; it++) {
        float y0, y1;
        matvec256(sm, rf2, sbase, xbase, chunk, y0, y1);
        if (chunk == 0) {
            const float w0 = sm[XS_OFF + row_lo];
            const float w1 = sm[XS_OFF + row_hi];
            // early-exit bookkeeping: has w moved during iteration it-1?
            const float dmax = fmaxf(fabsf(w0 - pw0), fabsf(w1 - pw1));
            pw0 = w0; pw1 = w1;
            if (dmax > 1e-7f) smi[FL_OFF + (it & 1)] = 1;
            const float g0 = fmaf(2.0f, y0, -beta0) + lam1 + 2.0f * lam2 * (w0 - wp0);
            const float g1 = fmaf(2.0f, y1, -beta1) + lam1 + 2.0f * lam2 * (w1 - wp1);
            sm[VS_OFF + row_lo] = fmaf(-step, g0, w0);
            sm[VS_OFF + row_hi] = fmaf(-step, g1, w1);
        }
        __syncthreads();

        // ---- projection: warp-replicated safeguarded Newton (no barriers) ----
        float vr[8];
#pragma unroll
        for (int k = 0; k < 8; k++) vr[k] = sm[VS_OFF + lane + 32 * k];

        const float tau = solve_tau(vr, tau_p, have_warm);
        tau_p = tau;
        have_warm = 1;

        // distributed write-back: warp w writes its 16 indices
        if (wsel) sm[XS_OFF + lane + 32 * kk] = fminf(fmaxf(vr[kk] - tau, 0.f), MAXW);
        if (tid == 0) smi[FL_OFF + ((it + 1) & 1)] = 0;   // reset next-iter flag
        __syncthreads();

        // The flag measures the delta taken during iteration it-1; at it==0 there is
        // no previous step -> never exit on the first iteration.
        if (it > 0 && smi[FL_OFF + (it & 1)] == 0) break; // fixpoint reached: done
    }

    // ---- post: renormalize w / (sum + eps) ----
    float s = 0.f;
#pragma unroll
    for (int k = 0; k < 8; k++) s += sm[XS_OFF + lane + 32 * k];
    s = bfly_add(s);
    const float inv = 1.0f / (s + EPSI);
    if (tid < 256) out[(size_t)b * PP + tid] = sm[XS_OFF + tid] * inv;
}

extern "C" void kernel_launch(void* const* d_in, const int* in_sizes, int n_in,
                              void* d_out, int out_size) {
    const float* sigma = (const float*)d_in[0];
    const float* beta  = (const float*)d_in[1];
    const float* wprev = (const float*)d_in[2];
    const float* ll1   = (const float*)d_in[3];
    const float* ll2   = (const float*)d_in[4];
    float* out = (float*)d_out;

    cudaFuncSetAttribute(drb_kernel, cudaFuncAttributeMaxDynamicSharedMemorySize, SMEM_BYTES);
    drb_kernel<<<BB, 512, SMEM_BYTES>>>(sigma, beta, wprev, ll1, ll2, out);
}

// round 17
// speedup vs baseline: 1.3210x; 1.3210x over previous
#include <cuda_runtime.h>
#include <math.h>

#define BB   512
#define PP   256
#define MAXW 0.1f
#define EPSI 1e-8f
#define NPGD 250
#define NPOW 20

#define RP        260                 // padded row length in floats (260 ≡ 4 mod 32 → conflict-free)
#define SROWS     128                 // rows of sigma kept in SMEM (rows 0..127)
#define SIG_WORDS (SROWS * RP)        // 33280
#define XS_OFF    SIG_WORDS           // current vector (w or power-iter v), 256 floats
#define VS_OFF    (SIG_WORDS + 256)   // staging vector, 256 floats
#define FL_OFF    (SIG_WORDS + 512)   // 2 ints: convergence flags (double-buffered)
#define TAU_OFF   (SIG_WORDS + 514)   // broadcast tau (float)
#define SMEM_WORDS (SIG_WORDS + 544)
#define SMEM_BYTES (SMEM_WORDS * 4)   // 135296 B

#define FPSCALE 33554432.0f           // 2^25 fixed point for clamped sums (max 25.6 -> fits s32)
#define FPONE   33554432

// 32-lane butterfly sum (cold paths only: power iteration + epilogue)
__device__ __forceinline__ float bfly_add(float v) {
#pragma unroll
    for (int o = 16; o >= 1; o >>= 1) v += __shfl_xor_sync(0xffffffffu, v, o);
    return v;
}

// monotone float <-> u32 key (order-preserving), for REDUX-based min/max
__device__ __forceinline__ unsigned fkey(float f) {
    int i = __float_as_int(f);
    unsigned u = (unsigned)i;
    return (i >= 0) ? (u | 0x80000000u) : ~u;
}
__device__ __forceinline__ float funkey(unsigned u) {
    return __int_as_float((u & 0x80000000u) ? (int)(u ^ 0x80000000u) : (int)(~u));
}

// packed f32x2 FMA: acc.lo += a.lo*b.lo, acc.hi += a.hi*b.hi  (FFMA2, PTX-only)
__device__ __forceinline__ void fma2(unsigned long long& acc,
                                     unsigned long long a, unsigned long long b) {
    asm("fma.rn.f32x2 %0, %1, %2, %0;" : "+l"(acc) : "l"(a), "l"(b));
}
__device__ __forceinline__ float pairsum(unsigned long long p) {
    float lo, hi;
    asm("mov.b64 {%0, %1}, %2;" : "=f"(lo), "=f"(hi) : "l"(p));
    return lo + hi;
}

// Bracket-safeguarded Newton for sum(clip(vr - tau, 0, MAXW)) == 1.
// Byte-identical semantics to the validated PASS solvers (R8/R15): bracket computed
// every call, warm start clamped into the bracket, 14-iter bisection-safeguarded.
// Now executed by ONE warp only (warp 0) — serial latency, zero ALU-throughput tax.
__device__ __forceinline__ float solve_tau(const float (&vr)[8], float tau0, int warm) {
    float mn = fminf(fminf(fminf(vr[0], vr[1]), fminf(vr[2], vr[3])),
                     fminf(fminf(vr[4], vr[5]), fminf(vr[6], vr[7])));
    float mx = fmaxf(fmaxf(fmaxf(vr[0], vr[1]), fmaxf(vr[2], vr[3])),
                     fmaxf(fmaxf(vr[4], vr[5]), fmaxf(vr[6], vr[7])));
    mn = funkey(__reduce_min_sync(0xffffffffu, fkey(mn)));
    mx = funkey(__reduce_max_sync(0xffffffffu, fkey(mx)));
    float lo = mn - MAXW, hi = mx;           // s(lo)=25.6>=1, s(hi)=0<=1: valid bracket
    float tau = warm ? fminf(fmaxf(tau0, lo), hi) : 0.5f * (lo + hi);

    for (int i = 0; i < 14; i++) {
        float s = 0.f; int m = 0;
#pragma unroll
        for (int k = 0; k < 8; k++) {
            const float d = vr[k] - tau;
            s += fminf(fmaxf(d, 0.f), MAXW);
            m += (d > 0.f) && (d < MAXW);
        }
        int si = __float2int_rn(s * FPSCALE);
        si = __reduce_add_sync(0xffffffffu, si);
        m  = __reduce_add_sync(0xffffffffu, m);
        const int err = si - FPONE;
        if (err >= -1 && err <= 1) return tau;            // |s-1| small: done
        if (err > 0) lo = tau; else hi = tau;
        if (hi - lo < 1e-9f) break;
        float t = (m > 0) ? fmaf((float)err, (1.0f / FPSCALE) / (float)m, tau)
                          : 0.5f * (lo + hi);
        tau = (t > lo && t < hi) ? t : 0.5f * (lo + hi);  // safeguard
    }
    return 0.5f * (lo + hi);
}

// Mat-vec: y = sigma * x. Rows 0..127 from SMEM, rows 128..255 from register file
// rf2[32] (f32x2-packed). Thread t: row_lo=t>>2, row_hi=128+(t>>2), chunk=t&3,
// cols staggered per chunk so the 4 chunks of a row-group hit distinct bank groups.
__device__ __forceinline__ void matvec256(const float* __restrict__ sm,
                                          const unsigned long long (&rf2)[32],
                                          int sbase, int xbase, int chunk,
                                          float& Y0, float& Y1) {
    unsigned long long A0 = 0ull, B0 = 0ull, A1 = 0ull, B1 = 0ull;
#pragma unroll
    for (int i = 0; i < 16; i++) {
        const int cm = 4 * ((i + 2 * chunk) & 15);
        const ulonglong2 xv = *reinterpret_cast<const ulonglong2*>(&sm[xbase + cm]);
        const ulonglong2 sv = *reinterpret_cast<const ulonglong2*>(&sm[sbase + cm]);
        fma2(A0, sv.x, xv.x);
        fma2(B0, sv.y, xv.y);
        fma2(A1, rf2[2 * i + 0], xv.x);
        fma2(B1, rf2[2 * i + 1], xv.y);
    }
    float r0 = pairsum(A0) + pairsum(B0);
    float r1 = pairsum(A1) + pairsum(B1);
    r0 += __shfl_xor_sync(0xffffffffu, r0, 1);
    r1 += __shfl_xor_sync(0xffffffffu, r1, 1);
    r0 += __shfl_xor_sync(0xffffffffu, r0, 2);
    r1 += __shfl_xor_sync(0xffffffffu, r1, 2);
    Y0 = r0; Y1 = r1;
}

__global__ __launch_bounds__(512, 1)
void drb_kernel(const float* __restrict__ sigma,
                const float* __restrict__ beta,
                const float* __restrict__ wprev,
                const float* __restrict__ ll1,
                const float* __restrict__ ll2,
                float* __restrict__ out) {
    extern __shared__ float sm[];
    int* const smi = reinterpret_cast<int*>(sm);
    const int tid    = threadIdx.x;
    const int b      = blockIdx.x;
    const int chunk  = tid & 3;
    const int col0   = chunk * 64;
    const int row_lo = tid >> 2;          // 0..127
    const int row_hi = 128 + row_lo;      // 128..255
    const int lane   = tid & 31;
    const int wid    = tid >> 5;          // 0..15
    const int sbase  = row_lo * RP + col0;
    const int xbase  = XS_OFF + col0;

    const float lam1 = expf(ll1[0]);
    const float lam2 = expf(ll2[0]);

    const size_t gb = (size_t)b * PP * PP;

    // ---- register-resident half of sigma (rows 128..255), f32x2-packed, staggered ----
    unsigned long long rf2[32];
    {
        const float* grow = sigma + gb + (size_t)row_hi * PP + col0;
#pragma unroll
        for (int i = 0; i < 16; i++) {
            const int cm = 4 * ((i + 2 * chunk) & 15);
            const ulonglong2 v = *reinterpret_cast<const ulonglong2*>(&grow[cm]);
            rf2[2 * i + 0] = v.x;
            rf2[2 * i + 1] = v.y;
        }
    }

    // ---- SMEM-resident half of sigma (rows 0..127), padded rows ----
    for (int idx = tid; idx < SROWS * 64; idx += 512) {
        const int r = idx >> 6, c4 = idx & 63;
        const float4 v = *reinterpret_cast<const float4*>(&sigma[gb + (size_t)r * PP + c4 * 4]);
        *reinterpret_cast<float4*>(&sm[r * RP + c4 * 4]) = v;
    }

    const float beta0 = beta[b * PP + row_lo];
    const float beta1 = beta[b * PP + row_hi];
    const float wp0   = wprev[b * PP + row_lo];
    const float wp1   = wprev[b * PP + row_hi];

    // ---- power iteration: v0 = 1/sqrt(P) ----
    if (tid < 256) sm[XS_OFF + tid] = 0.0625f;
    __syncthreads();

    for (int it = 0; it < NPOW; it++) {
        float u0, u1;
        matvec256(sm, rf2, sbase, xbase, chunk, u0, u1);
        if (chunk == 0) { sm[VS_OFF + row_lo] = u0; sm[VS_OFF + row_hi] = u1; }
        __syncthreads();
        float ns = 0.f;
#pragma unroll
        for (int k = 0; k < 8; k++) {
            const float t = sm[VS_OFF + lane + 32 * k];
            ns = fmaf(t, t, ns);
        }
        ns = bfly_add(ns);
        const float inv = 1.0f / (sqrtf(ns) + EPSI);
        if (tid < 256) sm[XS_OFF + tid] = sm[VS_OFF + tid] * inv;
        __syncthreads();
    }

    // ---- lmax = v' S v, step = 1/(2 lmax + 2 lam2 + 1e-6) ----
    float step;
    {
        float u0, u1;
        matvec256(sm, rf2, sbase, xbase, chunk, u0, u1);
        if (chunk == 0) {
            sm[VS_OFF + row_lo] = u0 * sm[XS_OFF + row_lo];
            sm[VS_OFF + row_hi] = u1 * sm[XS_OFF + row_hi];
        }
        __syncthreads();
        float lm = 0.f;
#pragma unroll
        for (int k = 0; k < 8; k++) lm += sm[VS_OFF + lane + 32 * k];
        lm = bfly_add(lm);
        step = 1.0f / (2.0f * lm + 2.0f * lam2 + 1e-6f);
        if (tid < 256) sm[XS_OFF + tid] = 1.0f / 256.0f;   // w0 = 1/P
        if (tid < 2)   smi[FL_OFF + tid] = 0;              // convergence flags
        __syncthreads();
    }

    float tau_p = 0.f;                                     // only warp 0's copy used
    int   have_warm = 0;
    float pw0 = 1.0f / 256.0f, pw1 = 1.0f / 256.0f;        // prev w for early-exit check

    // ---- projected gradient descent ----
    for (int it = 0; it < NPGD; it++) {
        float y0, y1;
        matvec256(sm, rf2, sbase, xbase, chunk, y0, y1);
        if (chunk == 0) {
            const float w0 = sm[XS_OFF + row_lo];
            const float w1 = sm[XS_OFF + row_hi];
            // early-exit bookkeeping: has w moved during iteration it-1?
            const float dmax = fmaxf(fabsf(w0 - pw0), fabsf(w1 - pw1));
            pw0 = w0; pw1 = w1;
            if (dmax > 1e-7f) smi[FL_OFF + (it & 1)] = 1;
            const float g0 = fmaf(2.0f, y0, -beta0) + lam1 + 2.0f * lam2 * (w0 - wp0);
            const float g1 = fmaf(2.0f, y1, -beta1) + lam1 + 2.0f * lam2 * (w1 - wp1);
            sm[VS_OFF + row_lo] = fmaf(-step, g0, w0);
            sm[VS_OFF + row_hi] = fmaf(-step, g1, w1);
        }
        __syncthreads();

        // ---- projection: SINGLE-WARP safeguarded Newton; others wait at barrier ----
        if (wid == 0) {
            float vr[8];
#pragma unroll
            for (int k = 0; k < 8; k++) vr[k] = sm[VS_OFF + lane + 32 * k];
            const float tau = solve_tau(vr, tau_p, have_warm);
            tau_p = tau;
            if (lane == 0) sm[TAU_OFF] = tau;
        }
        have_warm = 1;
        __syncthreads();

        // parallel write-back: 256 threads, one element each
        const float tau = sm[TAU_OFF];
        if (tid < 256)
            sm[XS_OFF + tid] = fminf(fmaxf(sm[VS_OFF + tid] - tau, 0.f), MAXW);
        if (tid == 0) smi[FL_OFF + ((it + 1) & 1)] = 0;   // reset next-iter flag
        __syncthreads();

        // The flag measures the delta taken during iteration it-1; at it==0 there is
        // no previous step -> never exit on the first iteration.
        if (it > 0 && smi[FL_OFF + (it & 1)] == 0) break; // fixpoint reached: done
    }

    // ---- post: renormalize w / (sum + eps) ----
    float s = 0.f;
#pragma unroll
    for (int k = 0; k < 8; k++) s += sm[XS_OFF + lane + 32 * k];
    s = bfly_add(s);
    const float inv = 1.0f / (s + EPSI);
    if (tid < 256) out[(size_t)b * PP + tid] = sm[XS_OFF + tid] * inv;
}

extern "C" void kernel_launch(void* const* d_in, const int* in_sizes, int n_in,
                              void* d_out, int out_size) {
    const float* sigma = (const float*)d_in[0];
    const float* beta  = (const float*)d_in[1];
    const float* wprev = (const float*)d_in[2];
    const float* ll1   = (const float*)d_in[3];
    const float* ll2   = (const float*)d_in[4];
    float* out = (float*)d_out;

    cudaFuncSetAttribute(drb_kernel, cudaFuncAttributeMaxDynamicSharedMemorySize, SMEM_BYTES);
    drb_kernel<<<BB, 512, SMEM_BYTES>>>(sigma, beta, wprev, ll1, ll2, out);
}